// round 11
// baseline (speedup 1.0000x reference)
#include <cuda_runtime.h>
#include <cuda_fp16.h>
#include <cmath>
#include <cstdint>

// ---------------- problem constants ----------------
#define BT    8192
#define DDIM  4096
#define NH    512
#define NDD   128
#define NTOT  640
#define KDIM  128

#define W2_BASE  (BT * 4 * 2 * 32)   // 2,097,152
#define DD_BASE  (2 * W2_BASE)

// ---------------- device scratch ----------------
__device__ __half g_Wh[(size_t)NTOT * DDIM];      // [n][k] fp16
__device__ __half g_Qh[4 * KDIM * KDIM];          // qkwT fp16: [c][j][k]

__device__ __forceinline__ float gelu_exact(float x) {
    return 0.5f * x * (1.0f + erff(x * 0.70710678118654752f));
}

#define CPA16(dst, src) \
    asm volatile("cp.async.cg.shared.global [%0], [%1], 16;" :: "r"(dst), "l"(src) : "memory")
#define CPA16_CA(dst, src) \
    asm volatile("cp.async.ca.shared.global [%0], [%1], 16;" :: "r"(dst), "l"(src) : "memory")
#define CPA_COMMIT() asm volatile("cp.async.commit_group;" ::: "memory")
#define CPA_WAIT2()  asm volatile("cp.async.wait_group 2;" ::: "memory")
#define CPA_WAIT1()  asm volatile("cp.async.wait_group 1;" ::: "memory")
#define CPA_WAIT0()  asm volatile("cp.async.wait_group 0;" ::: "memory")

__device__ __forceinline__ uint32_t smem_u32(const void* p) {
    uint32_t a;
    asm("{ .reg .u64 t; cvta.to.shared.u64 t, %1; cvt.u32.u64 %0, t; }" : "=r"(a) : "l"(p));
    return a;
}

__device__ __forceinline__ void mma16816(float* d, const uint32_t* a, const uint32_t* b) {
    asm volatile(
        "mma.sync.aligned.m16n8k16.row.col.f32.f16.f16.f32 "
        "{%0,%1,%2,%3}, {%4,%5,%6,%7}, {%8,%9}, {%0,%1,%2,%3};"
        : "+f"(d[0]), "+f"(d[1]), "+f"(d[2]), "+f"(d[3])
        : "r"(a[0]), "r"(a[1]), "r"(a[2]), "r"(a[3]), "r"(b[0]), "r"(b[1]));
}

__device__ __forceinline__ void ldsm_x4(uint32_t addr, uint32_t* r) {
    asm volatile("ldmatrix.sync.aligned.m8n8.x4.shared.b16 {%0,%1,%2,%3}, [%4];"
        : "=r"(r[0]), "=r"(r[1]), "=r"(r[2]), "=r"(r[3]) : "r"(addr));
}

__device__ __forceinline__ uint32_t pack_h2(float a, float b) {
    __half2 h = __floats2half2_rn(a, b);
    return *reinterpret_cast<uint32_t*>(&h);
}

// ---------------------------------------------------------------------------
// conv_w: transpose [dw1 | dd_p] -> Wh [640][4096] fp16 (K-major)
// ---------------------------------------------------------------------------
__global__ __launch_bounds__(256) void conv_w(const float* __restrict__ dw1,
                                              const float* __restrict__ ddp) {
    __shared__ float t[32][33];
    int n0 = blockIdx.x * 32, k0 = blockIdx.y * 32;
    int tx = threadIdx.x, ty = threadIdx.y;
    const float* src = (n0 < NH) ? dw1 : ddp;
    int ld   = (n0 < NH) ? NH : NDD;
    int ncol = (n0 < NH) ? (n0 + tx) : (n0 - NH + tx);
    #pragma unroll
    for (int j = 0; j < 4; ++j)
        t[ty + 8 * j][tx] = src[(size_t)(k0 + ty + 8 * j) * ld + ncol];
    __syncthreads();
    #pragma unroll
    for (int j = 0; j < 4; ++j) {
        int n = n0 + ty + 8 * j, k = k0 + tx;
        g_Wh[(size_t)n * DDIM + k] = __float2half_rn(t[tx][ty + 8 * j]);
    }
}

// ---------------------------------------------------------------------------
// conv_q: transpose qkw [c][k][j] -> Qh [c][j][k] fp16
// ---------------------------------------------------------------------------
__global__ __launch_bounds__(256) void conv_q(const float* __restrict__ qkw) {
    __shared__ float t[32][33];
    int c = blockIdx.x, j0 = blockIdx.y * 32, k0 = blockIdx.z * 32;
    int tx = threadIdx.x, ty = threadIdx.y;
    #pragma unroll
    for (int jj = 0; jj < 4; ++jj)
        t[ty + 8 * jj][tx] = qkw[((c * KDIM) + (k0 + ty + 8 * jj)) * KDIM + j0 + tx];
    __syncthreads();
    #pragma unroll
    for (int jj = 0; jj < 4; ++jj) {
        int j = j0 + ty + 8 * jj, k = k0 + tx;
        g_Qh[(c * KDIM + j) * KDIM + k] = __float2half_rn(t[tx][ty + 8 * jj]);
    }
}

// ---------------------------------------------------------------------------
// gemm1_mma: [8192,4096] x [4096,640], single-term fp16, f32 accumulator.
// CTA 32x128, BK=32, 128 threads (warp grid 1Mx4N, warp tile 32x32), occ 5.
// blockIdx.x = mtile (fast) so co-resident CTAs share the W stream (L1 via .ca).
// Smem (40K): mainloop A 2x2K [0,4K) + W 4x8K [4K,36K);
// epilogue Ahi [0,8K), Q double-buffer [8K,24K)+[24K,40K).
// ntile<4: fused 2nd GEMM (gelu -> fp16 1-term, Q 1-term) + RMS.
// ntile==4: tanh -> dd.
// ---------------------------------------------------------------------------
#define ABUF_B  2048
#define WST_B   8192
#define W_OFF   4096
#define GEMM1_SMEM 40960

__global__ __launch_bounds__(128, 5) void gemm1_mma(
    const float* __restrict__ X,
    float* __restrict__ w1n_out, float* __restrict__ w2_out,
    float* __restrict__ dd_out) {
    extern __shared__ char smem[];
    uint32_t sb = smem_u32(smem);

    const int tid  = threadIdx.x;
    const int wid  = tid >> 5;
    const int lane = tid & 31;
    const int gq   = lane >> 2;
    const int tg   = lane & 3;

    const int ntile = blockIdx.y;          // 0..4 (slow — shared by co-resident CTAs)
    const int mbase = blockIdx.x << 5;     // 32-row tiles (fast)
    const int n0w   = wid * 32;            // warp N offset

    const float* Xrow = X + (size_t)mbase * DDIM;
    const __half* Whrow = g_Wh + (size_t)(ntile * 128) * DDIM;

    // A LDG geometry: 32 rows x 32 k f32 = 256 16B chunks -> 2 per thread
    int aRow[2], aCh[2];
    uint32_t aSts[2];
    #pragma unroll
    for (int q = 0; q < 2; ++q) {
        int cc = tid + q * 128;
        aRow[q] = cc >> 3; aCh[q] = cc & 7;
        aSts[q] = (uint32_t)(aRow[q] * 64
                + ((((aCh[q] >> 1) ^ ((aRow[q] >> 1) & 3)) << 4) + ((aCh[q] & 1) << 3)));
    }
    // W cp.async geometry: 128 rows x 64B = 512 chunks -> 4 per thread
    int wRow[4], wCh[4];
    #pragma unroll
    for (int q = 0; q < 4; ++q) { int cc = tid + q * 128; wRow[q] = cc >> 2; wCh[q] = cc & 3; }

    auto w_refill = [&](uint32_t stg, int k0) {
        #pragma unroll
        for (int q = 0; q < 4; ++q) {
            uint32_t dst = stg + wRow[q] * 64
                         + (uint32_t)((wCh[q] ^ ((wRow[q] >> 1) & 3)) << 4);
            CPA16_CA(dst, Whrow + (size_t)wRow[q] * DDIM + k0 + wCh[q] * 8);
        }
    };

    float4 xreg[2];
    auto a_ldg = [&](int k0) {
        #pragma unroll
        for (int q = 0; q < 2; ++q)
            xreg[q] = *reinterpret_cast<const float4*>(
                &Xrow[(size_t)aRow[q] * DDIM + k0 + aCh[q] * 4]);
    };
    auto a_sts = [&](uint32_t abuf) {
        #pragma unroll
        for (int q = 0; q < 2; ++q) {
            float4 v = xreg[q];
            uint32_t h0 = pack_h2(v.x, v.y), h1 = pack_h2(v.z, v.w);
            uint32_t a = abuf + aSts[q];
            asm volatile("st.shared.v2.u32 [%0], {%1,%2};" :: "r"(a), "r"(h0), "r"(h1) : "memory");
        }
    };

    // ldmatrix lane geometry
    const int rowAoff = ((lane >> 3) & 1) * 8 + (lane & 7);
    const int cAoff   = (lane >> 4) & 1;
    const int rowBoff = ((lane >> 4) & 1) * 8 + (lane & 7);
    const int cBoff   = (lane >> 3) & 1;

    // ---- prologue ----
    a_ldg(0);
    a_sts(sb);
    a_ldg(32);
    w_refill(sb + W_OFF, 0);              CPA_COMMIT();
    w_refill(sb + W_OFF + WST_B, 32);     CPA_COMMIT();
    w_refill(sb + W_OFF + 2 * WST_B, 64); CPA_COMMIT();

    float acc[2][4][4];
    #pragma unroll
    for (int mi = 0; mi < 2; ++mi)
        #pragma unroll
        for (int ni = 0; ni < 4; ++ni)
            #pragma unroll
            for (int r = 0; r < 4; ++r) acc[mi][ni][r] = 0.0f;

    const int NKT = DDIM / 32;  // 128

    for (int it = 0; it < NKT; ++it) {
        uint32_t abuf = sb + (uint32_t)(it & 1) * ABUF_B;
        uint32_t wstg = sb + W_OFF + (uint32_t)(it & 3) * WST_B;

        CPA_WAIT2();
        __syncthreads();

        if (it + 1 < NKT) a_sts(sb + (uint32_t)((it + 1) & 1) * ABUF_B);
        if (it + 2 < NKT) a_ldg((it + 2) * 32);

        #pragma unroll
        for (int ks = 0; ks < 2; ++ks) {
            int c0 = ks * 2;
            uint32_t bh[4][2];
            #pragma unroll
            for (int p = 0; p < 2; ++p) {
                int rowB = n0w + p * 16 + rowBoff;
                int cB   = c0 + cBoff;
                uint32_t aW = wstg + rowB * 64
                            + (uint32_t)((cB ^ ((rowB >> 1) & 3)) << 4);
                uint32_t t[4];
                ldsm_x4(aW, t);
                bh[2*p][0] = t[0]; bh[2*p][1] = t[1];
                bh[2*p+1][0] = t[2]; bh[2*p+1][1] = t[3];
            }
            #pragma unroll
            for (int mi = 0; mi < 2; ++mi) {
                int rowA = mi * 16 + rowAoff;
                int cA   = c0 + cAoff;
                uint32_t aA = abuf + rowA * 64
                            + (uint32_t)((cA ^ ((rowA >> 1) & 3)) << 4);
                uint32_t ah[4];
                ldsm_x4(aA, ah);
                #pragma unroll
                for (int ni = 0; ni < 4; ++ni)
                    mma16816(acc[mi][ni], ah, bh[ni]);
            }
        }

        if (it + 3 < NKT)
            w_refill(sb + W_OFF + (uint32_t)((it + 3) & 3) * WST_B, (it + 3) * 32);
        CPA_COMMIT();
    }

    CPA_WAIT0();
    __syncthreads();

    // ================= epilogue =================
    if (ntile == 4) {
        #pragma unroll
        for (int mi = 0; mi < 2; ++mi) {
            #pragma unroll
            for (int ni = 0; ni < 4; ++ni) {
                int row = mbase + mi * 16 + gq;
                int col = n0w + ni * 8 + tg * 2;
                float2 o0 = make_float2(tanhf(acc[mi][ni][0]), tanhf(acc[mi][ni][1]));
                float2 o1 = make_float2(tanhf(acc[mi][ni][2]), tanhf(acc[mi][ni][3]));
                *reinterpret_cast<float2*>(&dd_out[(size_t)row * NDD + col])       = o0;
                *reinterpret_cast<float2*>(&dd_out[(size_t)(row + 8) * NDD + col]) = o1;
            }
        }
        return;
    }

    const int c = ntile;
    const uint32_t qb0 = sb + 8192;    // Q kb=0 [8K,24K)
    const uint32_t qb1 = sb + 24576;   // Q kb=1 [24K,40K)

    // Issue BOTH Q halves now; they land under the gelu/STS phase below.
    #pragma unroll
    for (int q = 0; q < 8; ++q) {
        int cc = tid + q * 128;
        int j  = cc >> 3, ch = cc & 7;
        uint32_t off = (uint32_t)(j * 128 + ((ch ^ (j & 7)) << 4));
        CPA16_CA(qb0 + off, g_Qh + ((size_t)(c * KDIM + j)) * KDIM + ch * 8);
    }
    CPA_COMMIT();
    #pragma unroll
    for (int q = 0; q < 8; ++q) {
        int cc = tid + q * 128;
        int j  = cc >> 3, ch = cc & 7;
        uint32_t off = (uint32_t)(j * 128 + ((ch ^ (j & 7)) << 4));
        CPA16_CA(qb1 + off, g_Qh + ((size_t)(c * KDIM + j)) * KDIM + 64 + ch * 8);
    }
    CPA_COMMIT();

    // Phase 1: gelu -> fp16 single-term into Ahi [0,8K)
    // rows 256B (128 fp16), 16 chunks, swizzle ch ^ (row&7)
    #pragma unroll
    for (int mi = 0; mi < 2; ++mi) {
        #pragma unroll
        for (int ni = 0; ni < 4; ++ni) {
            int row0 = mi * 16 + gq;
            int col  = n0w + ni * 8 + tg * 2;
            uint32_t ch = (uint32_t)(col >> 3);
            uint32_t wi = (uint32_t)((col & 7) * 2);
            #pragma unroll
            for (int r2 = 0; r2 < 2; ++r2) {
                int row = row0 + r2 * 8;
                float v0 = gelu_exact(acc[mi][ni][2 * r2 + 0]);
                float v1 = gelu_exact(acc[mi][ni][2 * r2 + 1]);
                uint32_t h = pack_h2(v0, v1);
                uint32_t a = sb + row * 256 + ((ch ^ (uint32_t)(row & 7)) << 4) + wi;
                asm volatile("st.shared.u32 [%0], %1;" :: "r"(a), "r"(h) : "memory");
            }
        }
    }

    // Phase 2: 32x128x128 single-term MMA (hh*qh), f32 acc, Q double-buffered
    float acc2[2][4][4];
    #pragma unroll
    for (int mi = 0; mi < 2; ++mi)
        #pragma unroll
        for (int ni = 0; ni < 4; ++ni)
            #pragma unroll
            for (int r = 0; r < 4; ++r) acc2[mi][ni][r] = 0.0f;

    for (int kb = 0; kb < 2; ++kb) {
        uint32_t qb = kb ? qb1 : qb0;
        if (kb == 0) { CPA_WAIT1(); } else { CPA_WAIT0(); }
        __syncthreads();   // Q half visible + phase-1 STS visible (kb0)

        #pragma unroll
        for (int ksl = 0; ksl < 4; ++ksl) {
            uint32_t qh[4][2];
            #pragma unroll
            for (int p = 0; p < 2; ++p) {
                int rowB = n0w + p * 16 + rowBoff;
                int cB   = ksl * 2 + cBoff;
                uint32_t aW = qb + rowB * 128
                            + (uint32_t)((cB ^ (rowB & 7)) << 4);
                uint32_t t[4];
                ldsm_x4(aW, t);
                qh[2*p][0] = t[0]; qh[2*p][1] = t[1];
                qh[2*p+1][0] = t[2]; qh[2*p+1][1] = t[3];
            }
            #pragma unroll
            for (int mi = 0; mi < 2; ++mi) {
                int rowA = mi * 16 + rowAoff;
                int cA   = kb * 8 + ksl * 2 + cAoff;
                uint32_t aA = sb + rowA * 256
                            + (uint32_t)((cA ^ (rowA & 7)) << 4);
                uint32_t ah[4];
                ldsm_x4(aA, ah);
                #pragma unroll
                for (int ni = 0; ni < 4; ++ni)
                    mma16816(acc2[mi][ni], ah, qh[ni]);
            }
        }
    }

    // Phase 3: RMS over M=32 (warp = one ii group) + stores
    const int ii = wid;
    #pragma unroll
    for (int mi = 0; mi < 2; ++mi) {
        #pragma unroll
        for (int r2 = 0; r2 < 2; ++r2) {
            int r = mbase + mi * 16 + gq + r2 * 8;
            float ss = 0.0f;
            #pragma unroll
            for (int ni = 0; ni < 4; ++ni) {
                ss = fmaf(acc2[mi][ni][2*r2+0], acc2[mi][ni][2*r2+0], ss);
                ss = fmaf(acc2[mi][ni][2*r2+1], acc2[mi][ni][2*r2+1], ss);
            }
            ss += __shfl_xor_sync(0xffffffffu, ss, 1);
            ss += __shfl_xor_sync(0xffffffffu, ss, 2);

            if (ii < 2) {
                float scale = rsqrtf(ss * (1.0f / 32.0f) + 1e-6f);
                #pragma unroll
                for (int ni = 0; ni < 4; ++ni) {
                    int m = ni * 8 + tg * 2;
                    float2 o = make_float2(acc2[mi][ni][2*r2+0] * scale,
                                           acc2[mi][ni][2*r2+1] * scale);
                    *reinterpret_cast<float2*>(
                        &w1n_out[(size_t)r * 256 + c * 64 + ii * 32 + m]) = o;
                }
            } else {
                #pragma unroll
                for (int ni = 0; ni < 4; ++ni) {
                    int m = ni * 8 + tg * 2;
                    float2 o = make_float2(acc2[mi][ni][2*r2+0],
                                           acc2[mi][ni][2*r2+1]);
                    *reinterpret_cast<float2*>(
                        &w2_out[(size_t)r * 256 + c * 64 + (ii - 2) * 32 + m]) = o;
                }
            }
        }
    }
}

// ---------------------------------------------------------------------------
extern "C" void kernel_launch(void* const* d_in, const int* in_sizes, int n_in,
                              void* d_out, int out_size) {
    const float* query = (const float*)d_in[0];
    // d_in[1] = key_vec (unused by reference)
    const float* dw1   = (const float*)d_in[2];
    const float* qkw   = (const float*)d_in[3];
    const float* dd_p  = (const float*)d_in[4];

    float* out = (float*)d_out;
    float* w1n = out;
    float* w2  = out + W2_BASE;
    float* dd  = out + DD_BASE;

    cudaFuncSetAttribute(gemm1_mma, cudaFuncAttributeMaxDynamicSharedMemorySize, GEMM1_SMEM);

    conv_w<<<dim3(NTOT / 32, DDIM / 32), dim3(32, 8)>>>(dw1, dd_p);
    conv_q<<<dim3(4, 4, 4), dim3(32, 8)>>>(qkw);
    gemm1_mma<<<dim3(256, 5), 128, GEMM1_SMEM>>>(query, w1n, w2, dd);
}

// round 12
// speedup vs baseline: 1.7406x; 1.7406x over previous
#include <cuda_runtime.h>
#include <cuda_fp16.h>
#include <cmath>
#include <cstdint>

// ---------------- problem constants ----------------
#define BT    8192
#define DDIM  4096
#define NH    512
#define NDD   128
#define NTOT  640
#define KDIM  128

#define W2_BASE  (BT * 4 * 2 * 32)   // 2,097,152
#define DD_BASE  (2 * W2_BASE)

// ---------------- device scratch ----------------
__device__ __half g_Wh[(size_t)NTOT * DDIM];      // [n][k] fp16
__device__ __half g_Qh[4 * KDIM * KDIM];          // qkwT fp16: [c][j][k]

__device__ __forceinline__ float gelu_exact(float x) {
    return 0.5f * x * (1.0f + erff(x * 0.70710678118654752f));
}

#define CPA16(dst, src) \
    asm volatile("cp.async.cg.shared.global [%0], [%1], 16;" :: "r"(dst), "l"(src) : "memory")
#define CPA_COMMIT() asm volatile("cp.async.commit_group;" ::: "memory")
#define CPA_WAIT2()  asm volatile("cp.async.wait_group 2;" ::: "memory")
#define CPA_WAIT1()  asm volatile("cp.async.wait_group 1;" ::: "memory")
#define CPA_WAIT0()  asm volatile("cp.async.wait_group 0;" ::: "memory")

__device__ __forceinline__ uint32_t smem_u32(const void* p) {
    uint32_t a;
    asm("{ .reg .u64 t; cvta.to.shared.u64 t, %1; cvt.u32.u64 %0, t; }" : "=r"(a) : "l"(p));
    return a;
}

__device__ __forceinline__ void mma16816(float* d, const uint32_t* a, const uint32_t* b) {
    asm volatile(
        "mma.sync.aligned.m16n8k16.row.col.f32.f16.f16.f32 "
        "{%0,%1,%2,%3}, {%4,%5,%6,%7}, {%8,%9}, {%0,%1,%2,%3};"
        : "+f"(d[0]), "+f"(d[1]), "+f"(d[2]), "+f"(d[3])
        : "r"(a[0]), "r"(a[1]), "r"(a[2]), "r"(a[3]), "r"(b[0]), "r"(b[1]));
}

__device__ __forceinline__ void ldsm_x4(uint32_t addr, uint32_t* r) {
    asm volatile("ldmatrix.sync.aligned.m8n8.x4.shared.b16 {%0,%1,%2,%3}, [%4];"
        : "=r"(r[0]), "=r"(r[1]), "=r"(r[2]), "=r"(r[3]) : "r"(addr));
}

__device__ __forceinline__ uint32_t pack_h2(float a, float b) {
    __half2 h = __floats2half2_rn(a, b);
    return *reinterpret_cast<uint32_t*>(&h);
}

// ---------------------------------------------------------------------------
// conv_w: transpose [dw1 | dd_p] -> Wh [640][4096] fp16 (K-major)
// ---------------------------------------------------------------------------
__global__ __launch_bounds__(256) void conv_w(const float* __restrict__ dw1,
                                              const float* __restrict__ ddp) {
    __shared__ float t[32][33];
    int n0 = blockIdx.x * 32, k0 = blockIdx.y * 32;
    int tx = threadIdx.x, ty = threadIdx.y;
    const float* src = (n0 < NH) ? dw1 : ddp;
    int ld   = (n0 < NH) ? NH : NDD;
    int ncol = (n0 < NH) ? (n0 + tx) : (n0 - NH + tx);
    #pragma unroll
    for (int j = 0; j < 4; ++j)
        t[ty + 8 * j][tx] = src[(size_t)(k0 + ty + 8 * j) * ld + ncol];
    __syncthreads();
    #pragma unroll
    for (int j = 0; j < 4; ++j) {
        int n = n0 + ty + 8 * j, k = k0 + tx;
        g_Wh[(size_t)n * DDIM + k] = __float2half_rn(t[tx][ty + 8 * j]);
    }
}

// ---------------------------------------------------------------------------
// conv_q: transpose qkw [c][k][j] -> Qh [c][j][k] fp16
// ---------------------------------------------------------------------------
__global__ __launch_bounds__(256) void conv_q(const float* __restrict__ qkw) {
    __shared__ float t[32][33];
    int c = blockIdx.x, j0 = blockIdx.y * 32, k0 = blockIdx.z * 32;
    int tx = threadIdx.x, ty = threadIdx.y;
    #pragma unroll
    for (int jj = 0; jj < 4; ++jj)
        t[ty + 8 * jj][tx] = qkw[((c * KDIM) + (k0 + ty + 8 * jj)) * KDIM + j0 + tx];
    __syncthreads();
    #pragma unroll
    for (int jj = 0; jj < 4; ++jj) {
        int j = j0 + ty + 8 * jj, k = k0 + tx;
        g_Qh[(c * KDIM + j) * KDIM + k] = __float2half_rn(t[tx][ty + 8 * jj]);
    }
}

// ---------------------------------------------------------------------------
// gemm_hidden: hidden cols only (ntiles 0..3) -> 512 CTAs (one occ-4 wave).
// CTA 64x128, BK=32, 128 threads (warp grid 2Mx2N, warp tile 32x64), occ 4.
// Smem (48K): mainloop A 2x4K [0,8K) + W 4x8K [8K,40K);
// epilogue Ahi [0,16K), Q double-buffer [16K,32K)+[32K,48K).
// Fused 2nd GEMM (gelu -> fp16 1-term, Q 1-term) + RMS -> w1n/w2.
// ---------------------------------------------------------------------------
#define ABUF_B  4096
#define WST_B   8192
#define W_OFF   8192
#define GEMM1_SMEM 49152

__global__ __launch_bounds__(128, 4) void gemm_hidden(
    const float* __restrict__ X,
    float* __restrict__ w1n_out, float* __restrict__ w2_out) {
    extern __shared__ char smem[];
    uint32_t sb = smem_u32(smem);

    const int tid  = threadIdx.x;
    const int wid  = tid >> 5;
    const int lane = tid & 31;
    const int gq   = lane >> 2;
    const int tg   = lane & 3;

    const int ntile = blockIdx.x;          // 0..3
    const int mbase = blockIdx.y << 6;     // 64-row tiles
    const int m0w   = (wid & 1) * 32;
    const int n0w   = (wid >> 1) * 64;

    const float* Xrow = X + (size_t)mbase * DDIM;
    const __half* Whrow = g_Wh + (size_t)(ntile * 128) * DDIM;

    // A LDG geometry: 64 rows x 32 k f32 = 512 16B chunks -> 4 per thread
    int aRow[4], aCh[4];
    uint32_t aSts[4];
    #pragma unroll
    for (int q = 0; q < 4; ++q) {
        int cc = tid + q * 128;
        aRow[q] = cc >> 3; aCh[q] = cc & 7;
        aSts[q] = (uint32_t)(aRow[q] * 64
                + ((((aCh[q] >> 1) ^ ((aRow[q] >> 1) & 3)) << 4) + ((aCh[q] & 1) << 3)));
    }
    // W cp.async geometry: 128 rows x 64B = 512 chunks -> 4 per thread
    int wRow[4], wCh[4];
    #pragma unroll
    for (int q = 0; q < 4; ++q) { int cc = tid + q * 128; wRow[q] = cc >> 2; wCh[q] = cc & 3; }

    auto w_refill = [&](uint32_t stg, int k0) {
        #pragma unroll
        for (int q = 0; q < 4; ++q) {
            uint32_t dst = stg + wRow[q] * 64
                         + (uint32_t)((wCh[q] ^ ((wRow[q] >> 1) & 3)) << 4);
            CPA16(dst, Whrow + (size_t)wRow[q] * DDIM + k0 + wCh[q] * 8);
        }
    };

    float4 xreg[4];
    auto a_ldg = [&](int k0) {
        #pragma unroll
        for (int q = 0; q < 4; ++q)
            xreg[q] = *reinterpret_cast<const float4*>(
                &Xrow[(size_t)aRow[q] * DDIM + k0 + aCh[q] * 4]);
    };
    auto a_sts = [&](uint32_t abuf) {
        #pragma unroll
        for (int q = 0; q < 4; ++q) {
            float4 v = xreg[q];
            uint32_t h0 = pack_h2(v.x, v.y), h1 = pack_h2(v.z, v.w);
            uint32_t a = abuf + aSts[q];
            asm volatile("st.shared.v2.u32 [%0], {%1,%2};" :: "r"(a), "r"(h0), "r"(h1) : "memory");
        }
    };

    // ldmatrix lane geometry
    const int rowAoff = ((lane >> 3) & 1) * 8 + (lane & 7);
    const int cAoff   = (lane >> 4) & 1;
    const int rowBoff = ((lane >> 4) & 1) * 8 + (lane & 7);
    const int cBoff   = (lane >> 3) & 1;

    // ---- prologue ----
    a_ldg(0);
    a_sts(sb);
    a_ldg(32);
    w_refill(sb + W_OFF, 0);              CPA_COMMIT();
    w_refill(sb + W_OFF + WST_B, 32);     CPA_COMMIT();
    w_refill(sb + W_OFF + 2 * WST_B, 64); CPA_COMMIT();

    float acc[2][8][4];
    #pragma unroll
    for (int mi = 0; mi < 2; ++mi)
        #pragma unroll
        for (int ni = 0; ni < 8; ++ni)
            #pragma unroll
            for (int r = 0; r < 4; ++r) acc[mi][ni][r] = 0.0f;

    const int NKT = DDIM / 32;  // 128

    for (int it = 0; it < NKT; ++it) {
        uint32_t abuf = sb + (uint32_t)(it & 1) * ABUF_B;
        uint32_t wstg = sb + W_OFF + (uint32_t)(it & 3) * WST_B;

        CPA_WAIT2();
        __syncthreads();

        if (it + 1 < NKT) a_sts(sb + (uint32_t)((it + 1) & 1) * ABUF_B);
        if (it + 2 < NKT) a_ldg((it + 2) * 32);

        #pragma unroll
        for (int ks = 0; ks < 2; ++ks) {
            int c0 = ks * 2;
            uint32_t bh[8][2];
            #pragma unroll
            for (int p = 0; p < 4; ++p) {
                int rowB = n0w + p * 16 + rowBoff;
                int cB   = c0 + cBoff;
                uint32_t aW = wstg + rowB * 64
                            + (uint32_t)((cB ^ ((rowB >> 1) & 3)) << 4);
                uint32_t t[4];
                ldsm_x4(aW, t);
                bh[2*p][0] = t[0]; bh[2*p][1] = t[1];
                bh[2*p+1][0] = t[2]; bh[2*p+1][1] = t[3];
            }
            #pragma unroll
            for (int mi = 0; mi < 2; ++mi) {
                int rowA = m0w + mi * 16 + rowAoff;
                int cA   = c0 + cAoff;
                uint32_t aA = abuf + rowA * 64
                            + (uint32_t)((cA ^ ((rowA >> 1) & 3)) << 4);
                uint32_t ah[4];
                ldsm_x4(aA, ah);
                #pragma unroll
                for (int ni = 0; ni < 8; ++ni)
                    mma16816(acc[mi][ni], ah, bh[ni]);
            }
        }

        if (it + 3 < NKT)
            w_refill(sb + W_OFF + (uint32_t)((it + 3) & 3) * WST_B, (it + 3) * 32);
        CPA_COMMIT();
    }

    CPA_WAIT0();
    __syncthreads();

    // ================= fused epilogue =================
    const int c = ntile;
    const uint32_t qb0 = sb + 16384;   // Q kb=0 [16K,32K)
    const uint32_t qb1 = sb + 32768;   // Q kb=1 [32K,48K)

    // Issue BOTH Q halves now; they land under the gelu/STS phase below.
    #pragma unroll
    for (int q = 0; q < 8; ++q) {
        int cc = tid + q * 128;
        int j  = cc >> 3, ch = cc & 7;
        uint32_t off = (uint32_t)(j * 128 + ((ch ^ (j & 7)) << 4));
        CPA16(qb0 + off, g_Qh + ((size_t)(c * KDIM + j)) * KDIM + ch * 8);
    }
    CPA_COMMIT();
    #pragma unroll
    for (int q = 0; q < 8; ++q) {
        int cc = tid + q * 128;
        int j  = cc >> 3, ch = cc & 7;
        uint32_t off = (uint32_t)(j * 128 + ((ch ^ (j & 7)) << 4));
        CPA16(qb1 + off, g_Qh + ((size_t)(c * KDIM + j)) * KDIM + 64 + ch * 8);
    }
    CPA_COMMIT();

    // Phase 1: gelu -> fp16 single-term into Ahi [0,16K)
    #pragma unroll
    for (int mi = 0; mi < 2; ++mi) {
        #pragma unroll
        for (int ni = 0; ni < 8; ++ni) {
            int row0 = m0w + mi * 16 + gq;
            int col  = n0w + ni * 8 + tg * 2;
            uint32_t ch = (uint32_t)(col >> 3);
            uint32_t wi = (uint32_t)((col & 7) * 2);
            #pragma unroll
            for (int r2 = 0; r2 < 2; ++r2) {
                int row = row0 + r2 * 8;
                float v0 = gelu_exact(acc[mi][ni][2 * r2 + 0]);
                float v1 = gelu_exact(acc[mi][ni][2 * r2 + 1]);
                uint32_t h = pack_h2(v0, v1);
                uint32_t a = sb + row * 256 + ((ch ^ (uint32_t)(row & 7)) << 4) + wi;
                asm volatile("st.shared.u32 [%0], %1;" :: "r"(a), "r"(h) : "memory");
            }
        }
    }

    // Phase 2: 64x128x128 single-term MMA (hh*qh), f32 acc, Q double-buffered
    float acc2[2][8][4];
    #pragma unroll
    for (int mi = 0; mi < 2; ++mi)
        #pragma unroll
        for (int ni = 0; ni < 8; ++ni)
            #pragma unroll
            for (int r = 0; r < 4; ++r) acc2[mi][ni][r] = 0.0f;

    for (int kb = 0; kb < 2; ++kb) {
        uint32_t qb = kb ? qb1 : qb0;
        if (kb == 0) { CPA_WAIT1(); } else { CPA_WAIT0(); }
        __syncthreads();

        #pragma unroll
        for (int ksl = 0; ksl < 4; ++ksl) {
            uint32_t qh[8][2];
            #pragma unroll
            for (int p = 0; p < 4; ++p) {
                int rowB = n0w + p * 16 + rowBoff;
                int cB   = ksl * 2 + cBoff;
                uint32_t aW = qb + rowB * 128
                            + (uint32_t)((cB ^ (rowB & 7)) << 4);
                uint32_t t[4];
                ldsm_x4(aW, t);
                qh[2*p][0] = t[0]; qh[2*p][1] = t[1];
                qh[2*p+1][0] = t[2]; qh[2*p+1][1] = t[3];
            }
            #pragma unroll
            for (int mi = 0; mi < 2; ++mi) {
                int rowA = m0w + mi * 16 + rowAoff;
                int cA   = kb * 8 + ksl * 2 + cAoff;
                uint32_t aA = sb + rowA * 256
                            + (uint32_t)((cA ^ (rowA & 7)) << 4);
                uint32_t ah[4];
                ldsm_x4(aA, ah);
                #pragma unroll
                for (int ni = 0; ni < 8; ++ni)
                    mma16816(acc2[mi][ni], ah, qh[ni]);
            }
        }
    }

    // Phase 3: RMS over 32-col groups + stores
    const int iiA = n0w >> 5;     // 0 (w1n pair) or 2 (w2 pair)
    #pragma unroll
    for (int mi = 0; mi < 2; ++mi) {
        #pragma unroll
        for (int r2 = 0; r2 < 2; ++r2) {
            int r = mbase + m0w + mi * 16 + gq + r2 * 8;
            float ssA = 0.0f, ssB = 0.0f;
            #pragma unroll
            for (int ni = 0; ni < 4; ++ni) {
                ssA = fmaf(acc2[mi][ni][2*r2+0], acc2[mi][ni][2*r2+0], ssA);
                ssA = fmaf(acc2[mi][ni][2*r2+1], acc2[mi][ni][2*r2+1], ssA);
                ssB = fmaf(acc2[mi][ni+4][2*r2+0], acc2[mi][ni+4][2*r2+0], ssB);
                ssB = fmaf(acc2[mi][ni+4][2*r2+1], acc2[mi][ni+4][2*r2+1], ssB);
            }
            ssA += __shfl_xor_sync(0xffffffffu, ssA, 1);
            ssA += __shfl_xor_sync(0xffffffffu, ssA, 2);
            ssB += __shfl_xor_sync(0xffffffffu, ssB, 1);
            ssB += __shfl_xor_sync(0xffffffffu, ssB, 2);

            if (iiA == 0) {
                float scA = rsqrtf(ssA * (1.0f / 32.0f) + 1e-6f);
                float scB = rsqrtf(ssB * (1.0f / 32.0f) + 1e-6f);
                #pragma unroll
                for (int ni = 0; ni < 4; ++ni) {
                    int m = ni * 8 + tg * 2;
                    float2 oA = make_float2(acc2[mi][ni][2*r2+0] * scA,
                                            acc2[mi][ni][2*r2+1] * scA);
                    float2 oB = make_float2(acc2[mi][ni+4][2*r2+0] * scB,
                                            acc2[mi][ni+4][2*r2+1] * scB);
                    *reinterpret_cast<float2*>(
                        &w1n_out[(size_t)r * 256 + c * 64 + m]) = oA;
                    *reinterpret_cast<float2*>(
                        &w1n_out[(size_t)r * 256 + c * 64 + 32 + m]) = oB;
                }
            } else {
                #pragma unroll
                for (int ni = 0; ni < 4; ++ni) {
                    int m = ni * 8 + tg * 2;
                    float2 oA = make_float2(acc2[mi][ni][2*r2+0],
                                            acc2[mi][ni][2*r2+1]);
                    float2 oB = make_float2(acc2[mi][ni+4][2*r2+0],
                                            acc2[mi][ni+4][2*r2+1]);
                    *reinterpret_cast<float2*>(
                        &w2_out[(size_t)r * 256 + c * 64 + m]) = oA;
                    *reinterpret_cast<float2*>(
                        &w2_out[(size_t)r * 256 + c * 64 + 32 + m]) = oB;
                }
            }
        }
    }
}

// ---------------------------------------------------------------------------
// gemm_dd: dd columns (cols 512..639), CTA 128x128, 256 threads, 64 CTAs.
// Warp grid 4Mx2N, warp tile 32x64 (same inner loop as gemm_hidden).
// Smem (48K): A 2x8K [0,16K) + W 4x8K [16K,48K).
// ---------------------------------------------------------------------------
#define DD_ABUF_B 8192
#define DD_W_OFF  16384
#define DD_SMEM   49152

__global__ __launch_bounds__(256, 2) void gemm_dd(
    const float* __restrict__ X, float* __restrict__ dd_out) {
    extern __shared__ char smem[];
    uint32_t sb = smem_u32(smem);

    const int tid  = threadIdx.x;
    const int wid  = tid >> 5;
    const int lane = tid & 31;
    const int gq   = lane >> 2;
    const int tg   = lane & 3;

    const int mbase = blockIdx.x << 7;     // 128-row tiles
    const int m0w   = (wid & 3) * 32;
    const int n0w   = (wid >> 2) * 64;

    const float* Xrow = X + (size_t)mbase * DDIM;
    const __half* Whrow = g_Wh + (size_t)NH * DDIM;   // dd block of W

    // A LDG geometry: 128 rows x 32 k f32 = 1024 chunks -> 4 per thread
    int aRow[4], aCh[4];
    uint32_t aSts[4];
    #pragma unroll
    for (int q = 0; q < 4; ++q) {
        int cc = tid + q * 256;
        aRow[q] = cc >> 3; aCh[q] = cc & 7;
        aSts[q] = (uint32_t)(aRow[q] * 64
                + ((((aCh[q] >> 1) ^ ((aRow[q] >> 1) & 3)) << 4) + ((aCh[q] & 1) << 3)));
    }
    // W: 128 rows x 64B = 512 chunks -> 2 per thread
    int wRow[2], wCh[2];
    #pragma unroll
    for (int q = 0; q < 2; ++q) { int cc = tid + q * 256; wRow[q] = cc >> 2; wCh[q] = cc & 3; }

    auto w_refill = [&](uint32_t stg, int k0) {
        #pragma unroll
        for (int q = 0; q < 2; ++q) {
            uint32_t dst = stg + wRow[q] * 64
                         + (uint32_t)((wCh[q] ^ ((wRow[q] >> 1) & 3)) << 4);
            CPA16(dst, Whrow + (size_t)wRow[q] * DDIM + k0 + wCh[q] * 8);
        }
    };

    float4 xreg[4];
    auto a_ldg = [&](int k0) {
        #pragma unroll
        for (int q = 0; q < 4; ++q)
            xreg[q] = *reinterpret_cast<const float4*>(
                &Xrow[(size_t)aRow[q] * DDIM + k0 + aCh[q] * 4]);
    };
    auto a_sts = [&](uint32_t abuf) {
        #pragma unroll
        for (int q = 0; q < 4; ++q) {
            float4 v = xreg[q];
            uint32_t h0 = pack_h2(v.x, v.y), h1 = pack_h2(v.z, v.w);
            uint32_t a = abuf + aSts[q];
            asm volatile("st.shared.v2.u32 [%0], {%1,%2};" :: "r"(a), "r"(h0), "r"(h1) : "memory");
        }
    };

    const int rowAoff = ((lane >> 3) & 1) * 8 + (lane & 7);
    const int cAoff   = (lane >> 4) & 1;
    const int rowBoff = ((lane >> 4) & 1) * 8 + (lane & 7);
    const int cBoff   = (lane >> 3) & 1;

    // ---- prologue ----
    a_ldg(0);
    a_sts(sb);
    a_ldg(32);
    w_refill(sb + DD_W_OFF, 0);              CPA_COMMIT();
    w_refill(sb + DD_W_OFF + WST_B, 32);     CPA_COMMIT();
    w_refill(sb + DD_W_OFF + 2 * WST_B, 64); CPA_COMMIT();

    float acc[2][8][4];
    #pragma unroll
    for (int mi = 0; mi < 2; ++mi)
        #pragma unroll
        for (int ni = 0; ni < 8; ++ni)
            #pragma unroll
            for (int r = 0; r < 4; ++r) acc[mi][ni][r] = 0.0f;

    const int NKT = DDIM / 32;  // 128

    for (int it = 0; it < NKT; ++it) {
        uint32_t abuf = sb + (uint32_t)(it & 1) * DD_ABUF_B;
        uint32_t wstg = sb + DD_W_OFF + (uint32_t)(it & 3) * WST_B;

        CPA_WAIT2();
        __syncthreads();

        if (it + 1 < NKT) a_sts(sb + (uint32_t)((it + 1) & 1) * DD_ABUF_B);
        if (it + 2 < NKT) a_ldg((it + 2) * 32);

        #pragma unroll
        for (int ks = 0; ks < 2; ++ks) {
            int c0 = ks * 2;
            uint32_t bh[8][2];
            #pragma unroll
            for (int p = 0; p < 4; ++p) {
                int rowB = n0w + p * 16 + rowBoff;
                int cB   = c0 + cBoff;
                uint32_t aW = wstg + rowB * 64
                            + (uint32_t)((cB ^ ((rowB >> 1) & 3)) << 4);
                uint32_t t[4];
                ldsm_x4(aW, t);
                bh[2*p][0] = t[0]; bh[2*p][1] = t[1];
                bh[2*p+1][0] = t[2]; bh[2*p+1][1] = t[3];
            }
            #pragma unroll
            for (int mi = 0; mi < 2; ++mi) {
                int rowA = m0w + mi * 16 + rowAoff;
                int cA   = c0 + cAoff;
                uint32_t aA = abuf + rowA * 64
                            + (uint32_t)((cA ^ ((rowA >> 1) & 3)) << 4);
                uint32_t ah[4];
                ldsm_x4(aA, ah);
                #pragma unroll
                for (int ni = 0; ni < 8; ++ni)
                    mma16816(acc[mi][ni], ah, bh[ni]);
            }
        }

        if (it + 3 < NKT)
            w_refill(sb + DD_W_OFF + (uint32_t)((it + 3) & 3) * WST_B, (it + 3) * 32);
        CPA_COMMIT();
    }

    // epilogue: tanh, direct row-major stores
    #pragma unroll
    for (int mi = 0; mi < 2; ++mi) {
        #pragma unroll
        for (int ni = 0; ni < 8; ++ni) {
            int row = mbase + m0w + mi * 16 + gq;
            int col = n0w + ni * 8 + tg * 2;
            float2 o0 = make_float2(tanhf(acc[mi][ni][0]), tanhf(acc[mi][ni][1]));
            float2 o1 = make_float2(tanhf(acc[mi][ni][2]), tanhf(acc[mi][ni][3]));
            *reinterpret_cast<float2*>(&dd_out[(size_t)row * NDD + col])       = o0;
            *reinterpret_cast<float2*>(&dd_out[(size_t)(row + 8) * NDD + col]) = o1;
        }
    }
}

// ---------------------------------------------------------------------------
extern "C" void kernel_launch(void* const* d_in, const int* in_sizes, int n_in,
                              void* d_out, int out_size) {
    const float* query = (const float*)d_in[0];
    // d_in[1] = key_vec (unused by reference)
    const float* dw1   = (const float*)d_in[2];
    const float* qkw   = (const float*)d_in[3];
    const float* dd_p  = (const float*)d_in[4];

    float* out = (float*)d_out;
    float* w1n = out;
    float* w2  = out + W2_BASE;
    float* dd  = out + DD_BASE;

    // one-time resources (created on the first, non-capturing correctness call)
    static cudaStream_t s2 = [] {
        cudaStream_t s; cudaStreamCreateWithFlags(&s, cudaStreamNonBlocking); return s;
    }();
    static cudaEvent_t evFork = [] {
        cudaEvent_t e; cudaEventCreateWithFlags(&e, cudaEventDisableTiming); return e;
    }();
    static cudaEvent_t evJoin = [] {
        cudaEvent_t e; cudaEventCreateWithFlags(&e, cudaEventDisableTiming); return e;
    }();

    cudaFuncSetAttribute(gemm_hidden, cudaFuncAttributeMaxDynamicSharedMemorySize, GEMM1_SMEM);
    cudaFuncSetAttribute(gemm_dd, cudaFuncAttributeMaxDynamicSharedMemorySize, DD_SMEM);

    conv_w<<<dim3(NTOT / 32, DDIM / 32), dim3(32, 8)>>>(dw1, dd_p);
    conv_q<<<dim3(4, 4, 4), dim3(32, 8)>>>(qkw);

    // fork: dd GEMM runs concurrently on s2
    cudaEventRecord(evFork, 0);
    cudaStreamWaitEvent(s2, evFork, 0);
    gemm_dd<<<64, 256, DD_SMEM, s2>>>(query, dd);

    gemm_hidden<<<dim3(4, 128), 128, GEMM1_SMEM>>>(query, w1n, w2);

    // join
    cudaEventRecord(evJoin, s2);
    cudaStreamWaitEvent(0, evJoin, 0);
}

// round 13
// speedup vs baseline: 2.2420x; 1.2880x over previous
#include <cuda_runtime.h>
#include <cuda_fp16.h>
#include <cmath>
#include <cstdint>

// ---------------- problem constants ----------------
#define BT    8192
#define DDIM  4096
#define NH    512
#define NDD   128
#define NTOT  640
#define KDIM  128

#define W2_BASE  (BT * 4 * 2 * 32)   // 2,097,152
#define DD_BASE  (2 * W2_BASE)

// ---------------- device scratch ----------------
__device__ __half g_Wh[(size_t)NTOT * DDIM];      // [n][k] fp16 (hidden 0..511, dd 512..639)
__device__ __half g_Qh[4 * KDIM * KDIM];          // qkwT fp16: [c][j][k]

__device__ __forceinline__ float gelu_exact(float x) {
    return 0.5f * x * (1.0f + erff(x * 0.70710678118654752f));
}

#define CPA16(dst, src) \
    asm volatile("cp.async.cg.shared.global [%0], [%1], 16;" :: "r"(dst), "l"(src) : "memory")
#define CPA_COMMIT() asm volatile("cp.async.commit_group;" ::: "memory")
#define CPA_WAIT2()  asm volatile("cp.async.wait_group 2;" ::: "memory")
#define CPA_WAIT1()  asm volatile("cp.async.wait_group 1;" ::: "memory")
#define CPA_WAIT0()  asm volatile("cp.async.wait_group 0;" ::: "memory")

__device__ __forceinline__ uint32_t smem_u32(const void* p) {
    uint32_t a;
    asm("{ .reg .u64 t; cvta.to.shared.u64 t, %1; cvt.u32.u64 %0, t; }" : "=r"(a) : "l"(p));
    return a;
}

__device__ __forceinline__ void mma16816(float* d, const uint32_t* a, const uint32_t* b) {
    asm volatile(
        "mma.sync.aligned.m16n8k16.row.col.f32.f16.f16.f32 "
        "{%0,%1,%2,%3}, {%4,%5,%6,%7}, {%8,%9}, {%0,%1,%2,%3};"
        : "+f"(d[0]), "+f"(d[1]), "+f"(d[2]), "+f"(d[3])
        : "r"(a[0]), "r"(a[1]), "r"(a[2]), "r"(a[3]), "r"(b[0]), "r"(b[1]));
}

__device__ __forceinline__ void ldsm_x4(uint32_t addr, uint32_t* r) {
    asm volatile("ldmatrix.sync.aligned.m8n8.x4.shared.b16 {%0,%1,%2,%3}, [%4];"
        : "=r"(r[0]), "=r"(r[1]), "=r"(r[2]), "=r"(r[3]) : "r"(addr));
}

__device__ __forceinline__ uint32_t pack_h2(float a, float b) {
    __half2 h = __floats2half2_rn(a, b);
    return *reinterpret_cast<uint32_t*>(&h);
}

// ---------------------------------------------------------------------------
// conv_w: transpose [dw1 | dd_p] -> Wh [640][4096] fp16 (K-major)
// ---------------------------------------------------------------------------
__global__ __launch_bounds__(256) void conv_w(const float* __restrict__ dw1,
                                              const float* __restrict__ ddp) {
    __shared__ float t[32][33];
    int n0 = blockIdx.x * 32, k0 = blockIdx.y * 32;
    int tx = threadIdx.x, ty = threadIdx.y;
    const float* src = (n0 < NH) ? dw1 : ddp;
    int ld   = (n0 < NH) ? NH : NDD;
    int ncol = (n0 < NH) ? (n0 + tx) : (n0 - NH + tx);
    #pragma unroll
    for (int j = 0; j < 4; ++j)
        t[ty + 8 * j][tx] = src[(size_t)(k0 + ty + 8 * j) * ld + ncol];
    __syncthreads();
    #pragma unroll
    for (int j = 0; j < 4; ++j) {
        int n = n0 + ty + 8 * j, k = k0 + tx;
        g_Wh[(size_t)n * DDIM + k] = __float2half_rn(t[tx][ty + 8 * j]);
    }
}

// ---------------------------------------------------------------------------
// conv_q: transpose qkw [c][k][j] -> Qh [c][j][k] fp16
// ---------------------------------------------------------------------------
__global__ __launch_bounds__(256) void conv_q(const float* __restrict__ qkw) {
    __shared__ float t[32][33];
    int c = blockIdx.x, j0 = blockIdx.y * 32, k0 = blockIdx.z * 32;
    int tx = threadIdx.x, ty = threadIdx.y;
    #pragma unroll
    for (int jj = 0; jj < 4; ++jj)
        t[ty + 8 * jj][tx] = qkw[((c * KDIM) + (k0 + ty + 8 * jj)) * KDIM + j0 + tx];
    __syncthreads();
    #pragma unroll
    for (int jj = 0; jj < 4; ++jj) {
        int j = j0 + ty + 8 * jj, k = k0 + tx;
        g_Qh[(c * KDIM + j) * KDIM + k] = __float2half_rn(t[tx][ty + 8 * jj]);
    }
}

// ---------------------------------------------------------------------------
// gemm_all: 512 CTAs (one occ-4 wave). CTA (ntile, mbase) computes:
//   hidden cols [ntile*128, +128) x 64 rows  -> fused 2nd GEMM + RMS -> w1n/w2
//   dd cols     [ntile*32,  +32)  x 64 rows  -> tanh -> dd
// CTA 64x160-equivalent, BK=32, 128 threads (warp grid 2Mx2N for hidden;
// dd n-split by nw = wid>>1), occ 4.
// Smem (48K): mainloop A 2x4K [0,8K) + W 4x10K [8K,48K) (W tile = 160 rows);
// epilogue Ahi [0,16K), Q double-buffer [16K,32K)+[32K,48K).
// ---------------------------------------------------------------------------
#define ABUF_B  4096
#define WST_B   10240
#define W_OFF   8192
#define GEMM1_SMEM 49152

__global__ __launch_bounds__(128, 4) void gemm_all(
    const float* __restrict__ X,
    float* __restrict__ w1n_out, float* __restrict__ w2_out,
    float* __restrict__ dd_out) {
    extern __shared__ char smem[];
    uint32_t sb = smem_u32(smem);

    const int tid  = threadIdx.x;
    const int wid  = tid >> 5;
    const int lane = tid & 31;
    const int gq   = lane >> 2;
    const int tg   = lane & 3;

    const int ntile = blockIdx.x;          // 0..3
    const int mbase = blockIdx.y << 6;     // 64-row tiles
    const int m0w   = (wid & 1) * 32;
    const int n0w   = (wid >> 1) * 64;
    const int nw    = wid >> 1;            // dd n-half 0..1

    const float* Xrow = X + (size_t)mbase * DDIM;

    // A LDG geometry: 64 rows x 32 k f32 = 512 16B chunks -> 4 per thread
    int aRow[4], aCh[4];
    uint32_t aSts[4];
    #pragma unroll
    for (int q = 0; q < 4; ++q) {
        int cc = tid + q * 128;
        aRow[q] = cc >> 3; aCh[q] = cc & 7;
        aSts[q] = (uint32_t)(aRow[q] * 64
                + ((((aCh[q] >> 1) ^ ((aRow[q] >> 1) & 3)) << 4) + ((aCh[q] & 1) << 3)));
    }
    // W cp.async geometry: 160 rows x 64B = 640 chunks -> 5 per thread
    uint32_t wDst[5];
    const __half* wSrc[5];
    #pragma unroll
    for (int q = 0; q < 5; ++q) {
        int cc = tid + q * 128;
        int r = cc >> 2, ch = cc & 3;
        wDst[q] = (uint32_t)(r * 64 + ((ch ^ ((r >> 1) & 3)) << 4));
        int grow = (r < 128) ? (ntile * 128 + r) : (NH + ntile * 32 + (r - 128));
        wSrc[q] = g_Wh + (size_t)grow * DDIM + ch * 8;
    }

    auto w_refill = [&](uint32_t stg, int k0) {
        #pragma unroll
        for (int q = 0; q < 5; ++q)
            CPA16(stg + wDst[q], wSrc[q] + k0);
    };

    float4 xreg[4];
    auto a_ldg = [&](int k0) {
        #pragma unroll
        for (int q = 0; q < 4; ++q)
            xreg[q] = *reinterpret_cast<const float4*>(
                &Xrow[(size_t)aRow[q] * DDIM + k0 + aCh[q] * 4]);
    };
    auto a_sts = [&](uint32_t abuf) {
        #pragma unroll
        for (int q = 0; q < 4; ++q) {
            float4 v = xreg[q];
            uint32_t h0 = pack_h2(v.x, v.y), h1 = pack_h2(v.z, v.w);
            uint32_t a = abuf + aSts[q];
            asm volatile("st.shared.v2.u32 [%0], {%1,%2};" :: "r"(a), "r"(h0), "r"(h1) : "memory");
        }
    };

    // ldmatrix lane geometry
    const int rowAoff = ((lane >> 3) & 1) * 8 + (lane & 7);
    const int cAoff   = (lane >> 4) & 1;
    const int rowBoff = ((lane >> 4) & 1) * 8 + (lane & 7);
    const int cBoff   = (lane >> 3) & 1;

    // ---- prologue ----
    a_ldg(0);
    a_sts(sb);
    a_ldg(32);
    w_refill(sb + W_OFF, 0);              CPA_COMMIT();
    w_refill(sb + W_OFF + WST_B, 32);     CPA_COMMIT();
    w_refill(sb + W_OFF + 2 * WST_B, 64); CPA_COMMIT();

    float acc[2][8][4];
    float accD[2][2][4];
    #pragma unroll
    for (int mi = 0; mi < 2; ++mi) {
        #pragma unroll
        for (int ni = 0; ni < 8; ++ni)
            #pragma unroll
            for (int r = 0; r < 4; ++r) acc[mi][ni][r] = 0.0f;
        #pragma unroll
        for (int ni = 0; ni < 2; ++ni)
            #pragma unroll
            for (int r = 0; r < 4; ++r) accD[mi][ni][r] = 0.0f;
    }

    const int NKT = DDIM / 32;  // 128

    for (int it = 0; it < NKT; ++it) {
        uint32_t abuf = sb + (uint32_t)(it & 1) * ABUF_B;
        uint32_t wstg = sb + W_OFF + (uint32_t)(it & 3) * WST_B;

        CPA_WAIT2();
        __syncthreads();

        if (it + 1 < NKT) a_sts(sb + (uint32_t)((it + 1) & 1) * ABUF_B);
        if (it + 2 < NKT) a_ldg((it + 2) * 32);

        #pragma unroll
        for (int ks = 0; ks < 2; ++ks) {
            int c0 = ks * 2;
            uint32_t bh[8][2], bd[2][2];
            #pragma unroll
            for (int p = 0; p < 4; ++p) {
                int rowB = n0w + p * 16 + rowBoff;
                int cB   = c0 + cBoff;
                uint32_t aW = wstg + rowB * 64
                            + (uint32_t)((cB ^ ((rowB >> 1) & 3)) << 4);
                uint32_t t[4];
                ldsm_x4(aW, t);
                bh[2*p][0] = t[0]; bh[2*p][1] = t[1];
                bh[2*p+1][0] = t[2]; bh[2*p+1][1] = t[3];
            }
            {   // dd W frags: rows 128 + nw*16 .. +16
                int rowD = 128 + nw * 16 + rowBoff;
                int cB   = c0 + cBoff;
                uint32_t aD = wstg + rowD * 64
                            + (uint32_t)((cB ^ ((rowD >> 1) & 3)) << 4);
                uint32_t t[4];
                ldsm_x4(aD, t);
                bd[0][0] = t[0]; bd[0][1] = t[1];
                bd[1][0] = t[2]; bd[1][1] = t[3];
            }
            #pragma unroll
            for (int mi = 0; mi < 2; ++mi) {
                int rowA = m0w + mi * 16 + rowAoff;
                int cA   = c0 + cAoff;
                uint32_t aA = abuf + rowA * 64
                            + (uint32_t)((cA ^ ((rowA >> 1) & 3)) << 4);
                uint32_t ah[4];
                ldsm_x4(aA, ah);
                #pragma unroll
                for (int ni = 0; ni < 8; ++ni)
                    mma16816(acc[mi][ni], ah, bh[ni]);
                mma16816(accD[mi][0], ah, bd[0]);
                mma16816(accD[mi][1], ah, bd[1]);
            }
        }

        if (it + 3 < NKT)
            w_refill(sb + W_OFF + (uint32_t)((it + 3) & 3) * WST_B, (it + 3) * 32);
        CPA_COMMIT();
    }

    CPA_WAIT0();
    __syncthreads();

    // ---- dd epilogue first (frees accD registers) ----
    #pragma unroll
    for (int mi = 0; mi < 2; ++mi) {
        #pragma unroll
        for (int fi = 0; fi < 2; ++fi) {
            int row = mbase + m0w + mi * 16 + gq;
            int col = ntile * 32 + nw * 16 + fi * 8 + tg * 2;
            float2 o0 = make_float2(tanhf(accD[mi][fi][0]), tanhf(accD[mi][fi][1]));
            float2 o1 = make_float2(tanhf(accD[mi][fi][2]), tanhf(accD[mi][fi][3]));
            *reinterpret_cast<float2*>(&dd_out[(size_t)row * NDD + col])       = o0;
            *reinterpret_cast<float2*>(&dd_out[(size_t)(row + 8) * NDD + col]) = o1;
        }
    }

    // ================= fused hidden epilogue =================
    const int c = ntile;
    const uint32_t qb0 = sb + 16384;   // Q kb=0 [16K,32K)
    const uint32_t qb1 = sb + 32768;   // Q kb=1 [32K,48K)

    // Issue BOTH Q halves now; they land under the gelu/STS phase below.
    #pragma unroll
    for (int q = 0; q < 8; ++q) {
        int cc = tid + q * 128;
        int j  = cc >> 3, ch = cc & 7;
        uint32_t off = (uint32_t)(j * 128 + ((ch ^ (j & 7)) << 4));
        CPA16(qb0 + off, g_Qh + ((size_t)(c * KDIM + j)) * KDIM + ch * 8);
    }
    CPA_COMMIT();
    #pragma unroll
    for (int q = 0; q < 8; ++q) {
        int cc = tid + q * 128;
        int j  = cc >> 3, ch = cc & 7;
        uint32_t off = (uint32_t)(j * 128 + ((ch ^ (j & 7)) << 4));
        CPA16(qb1 + off, g_Qh + ((size_t)(c * KDIM + j)) * KDIM + 64 + ch * 8);
    }
    CPA_COMMIT();

    // Phase 1: gelu -> fp16 single-term into Ahi [0,16K)
    #pragma unroll
    for (int mi = 0; mi < 2; ++mi) {
        #pragma unroll
        for (int ni = 0; ni < 8; ++ni) {
            int row0 = m0w + mi * 16 + gq;
            int col  = n0w + ni * 8 + tg * 2;
            uint32_t ch = (uint32_t)(col >> 3);
            uint32_t wi = (uint32_t)((col & 7) * 2);
            #pragma unroll
            for (int r2 = 0; r2 < 2; ++r2) {
                int row = row0 + r2 * 8;
                float v0 = gelu_exact(acc[mi][ni][2 * r2 + 0]);
                float v1 = gelu_exact(acc[mi][ni][2 * r2 + 1]);
                uint32_t h = pack_h2(v0, v1);
                uint32_t a = sb + row * 256 + ((ch ^ (uint32_t)(row & 7)) << 4) + wi;
                asm volatile("st.shared.u32 [%0], %1;" :: "r"(a), "r"(h) : "memory");
            }
        }
    }

    // Phase 2: 64x128x128 single-term MMA (hh*qh), f32 acc, Q double-buffered
    float acc2[2][8][4];
    #pragma unroll
    for (int mi = 0; mi < 2; ++mi)
        #pragma unroll
        for (int ni = 0; ni < 8; ++ni)
            #pragma unroll
            for (int r = 0; r < 4; ++r) acc2[mi][ni][r] = 0.0f;

    for (int kb = 0; kb < 2; ++kb) {
        uint32_t qb = kb ? qb1 : qb0;
        if (kb == 0) { CPA_WAIT1(); } else { CPA_WAIT0(); }
        __syncthreads();

        #pragma unroll
        for (int ksl = 0; ksl < 4; ++ksl) {
            uint32_t qh[8][2];
            #pragma unroll
            for (int p = 0; p < 4; ++p) {
                int rowB = n0w + p * 16 + rowBoff;
                int cB   = ksl * 2 + cBoff;
                uint32_t aW = qb + rowB * 128
                            + (uint32_t)((cB ^ (rowB & 7)) << 4);
                uint32_t t[4];
                ldsm_x4(aW, t);
                qh[2*p][0] = t[0]; qh[2*p][1] = t[1];
                qh[2*p+1][0] = t[2]; qh[2*p+1][1] = t[3];
            }
            #pragma unroll
            for (int mi = 0; mi < 2; ++mi) {
                int rowA = m0w + mi * 16 + rowAoff;
                int cA   = kb * 8 + ksl * 2 + cAoff;
                uint32_t aA = sb + rowA * 256
                            + (uint32_t)((cA ^ (rowA & 7)) << 4);
                uint32_t ah[4];
                ldsm_x4(aA, ah);
                #pragma unroll
                for (int ni = 0; ni < 8; ++ni)
                    mma16816(acc2[mi][ni], ah, qh[ni]);
            }
        }
    }

    // Phase 3: RMS over 32-col groups + stores
    const int iiA = n0w >> 5;     // 0 (w1n pair) or 2 (w2 pair)
    #pragma unroll
    for (int mi = 0; mi < 2; ++mi) {
        #pragma unroll
        for (int r2 = 0; r2 < 2; ++r2) {
            int r = mbase + m0w + mi * 16 + gq + r2 * 8;
            float ssA = 0.0f, ssB = 0.0f;
            #pragma unroll
            for (int ni = 0; ni < 4; ++ni) {
                ssA = fmaf(acc2[mi][ni][2*r2+0], acc2[mi][ni][2*r2+0], ssA);
                ssA = fmaf(acc2[mi][ni][2*r2+1], acc2[mi][ni][2*r2+1], ssA);
                ssB = fmaf(acc2[mi][ni+4][2*r2+0], acc2[mi][ni+4][2*r2+0], ssB);
                ssB = fmaf(acc2[mi][ni+4][2*r2+1], acc2[mi][ni+4][2*r2+1], ssB);
            }
            ssA += __shfl_xor_sync(0xffffffffu, ssA, 1);
            ssA += __shfl_xor_sync(0xffffffffu, ssA, 2);
            ssB += __shfl_xor_sync(0xffffffffu, ssB, 1);
            ssB += __shfl_xor_sync(0xffffffffu, ssB, 2);

            if (iiA == 0) {
                float scA = rsqrtf(ssA * (1.0f / 32.0f) + 1e-6f);
                float scB = rsqrtf(ssB * (1.0f / 32.0f) + 1e-6f);
                #pragma unroll
                for (int ni = 0; ni < 4; ++ni) {
                    int m = ni * 8 + tg * 2;
                    float2 oA = make_float2(acc2[mi][ni][2*r2+0] * scA,
                                            acc2[mi][ni][2*r2+1] * scA);
                    float2 oB = make_float2(acc2[mi][ni+4][2*r2+0] * scB,
                                            acc2[mi][ni+4][2*r2+1] * scB);
                    *reinterpret_cast<float2*>(
                        &w1n_out[(size_t)r * 256 + c * 64 + m]) = oA;
                    *reinterpret_cast<float2*>(
                        &w1n_out[(size_t)r * 256 + c * 64 + 32 + m]) = oB;
                }
            } else {
                #pragma unroll
                for (int ni = 0; ni < 4; ++ni) {
                    int m = ni * 8 + tg * 2;
                    float2 oA = make_float2(acc2[mi][ni][2*r2+0],
                                            acc2[mi][ni][2*r2+1]);
                    float2 oB = make_float2(acc2[mi][ni+4][2*r2+0],
                                            acc2[mi][ni+4][2*r2+1]);
                    *reinterpret_cast<float2*>(
                        &w2_out[(size_t)r * 256 + c * 64 + m]) = oA;
                    *reinterpret_cast<float2*>(
                        &w2_out[(size_t)r * 256 + c * 64 + 32 + m]) = oB;
                }
            }
        }
    }
}

// ---------------------------------------------------------------------------
extern "C" void kernel_launch(void* const* d_in, const int* in_sizes, int n_in,
                              void* d_out, int out_size) {
    const float* query = (const float*)d_in[0];
    // d_in[1] = key_vec (unused by reference)
    const float* dw1   = (const float*)d_in[2];
    const float* qkw   = (const float*)d_in[3];
    const float* dd_p  = (const float*)d_in[4];

    float* out = (float*)d_out;
    float* w1n = out;
    float* w2  = out + W2_BASE;
    float* dd  = out + DD_BASE;

    cudaFuncSetAttribute(gemm_all, cudaFuncAttributeMaxDynamicSharedMemorySize, GEMM1_SMEM);

    conv_w<<<dim3(NTOT / 32, DDIM / 32), dim3(32, 8)>>>(dw1, dd_p);
    conv_q<<<dim3(4, 4, 4), dim3(32, 8)>>>(qkw);
    gemm_all<<<dim3(4, 128), 128, GEMM1_SMEM>>>(query, w1n, w2, dd);
}

// round 14
// speedup vs baseline: 2.2600x; 1.0080x over previous
#include <cuda_runtime.h>
#include <cuda_fp16.h>
#include <cmath>
#include <cstdint>

// ---------------- problem constants ----------------
#define BT    8192
#define DDIM  4096
#define NH    512
#define NDD   128
#define NTOT  640
#define KDIM  128

#define W2_BASE  (BT * 4 * 2 * 32)   // 2,097,152
#define DD_BASE  (2 * W2_BASE)

// ---------------- device scratch ----------------
__device__ __half g_Wh[(size_t)NTOT * DDIM];      // [n][k] fp16 (hidden 0..511, dd 512..639)
__device__ __half g_Qh[4 * KDIM * KDIM];          // qkwT fp16: [c][j][k]

__device__ __forceinline__ float gelu_exact(float x) {
    return 0.5f * x * (1.0f + erff(x * 0.70710678118654752f));
}

#define CPA16(dst, src) \
    asm volatile("cp.async.cg.shared.global [%0], [%1], 16;" :: "r"(dst), "l"(src) : "memory")
#define CPA_COMMIT() asm volatile("cp.async.commit_group;" ::: "memory")
#define CPA_WAIT2()  asm volatile("cp.async.wait_group 2;" ::: "memory")
#define CPA_WAIT1()  asm volatile("cp.async.wait_group 1;" ::: "memory")
#define CPA_WAIT0()  asm volatile("cp.async.wait_group 0;" ::: "memory")

__device__ __forceinline__ uint32_t smem_u32(const void* p) {
    uint32_t a;
    asm("{ .reg .u64 t; cvta.to.shared.u64 t, %1; cvt.u32.u64 %0, t; }" : "=r"(a) : "l"(p));
    return a;
}

__device__ __forceinline__ void mma16816(float* d, const uint32_t* a, const uint32_t* b) {
    asm volatile(
        "mma.sync.aligned.m16n8k16.row.col.f32.f16.f16.f32 "
        "{%0,%1,%2,%3}, {%4,%5,%6,%7}, {%8,%9}, {%0,%1,%2,%3};"
        : "+f"(d[0]), "+f"(d[1]), "+f"(d[2]), "+f"(d[3])
        : "r"(a[0]), "r"(a[1]), "r"(a[2]), "r"(a[3]), "r"(b[0]), "r"(b[1]));
}

__device__ __forceinline__ void ldsm_x4(uint32_t addr, uint32_t* r) {
    asm volatile("ldmatrix.sync.aligned.m8n8.x4.shared.b16 {%0,%1,%2,%3}, [%4];"
        : "=r"(r[0]), "=r"(r[1]), "=r"(r[2]), "=r"(r[3]) : "r"(addr));
}

__device__ __forceinline__ uint32_t pack_h2(float a, float b) {
    __half2 h = __floats2half2_rn(a, b);
    return *reinterpret_cast<uint32_t*>(&h);
}

// ---------------------------------------------------------------------------
// conv_wq: merged weight-prep kernel.
//   blocks [0, 2560):   transpose [dw1 | dd_p] -> g_Wh [640][4096] fp16
//   blocks [2560, 2624): transpose qkw [c][k][j] -> g_Qh [c][j][k] fp16
// ---------------------------------------------------------------------------
__global__ __launch_bounds__(256) void conv_wq(const float* __restrict__ dw1,
                                               const float* __restrict__ ddp,
                                               const float* __restrict__ qkw) {
    __shared__ float t[32][33];
    int tx = threadIdx.x, ty = threadIdx.y;   // 32 x 8
    int bid = blockIdx.x;

    if (bid < 2560) {
        int n0 = (bid % 20) * 32, k0 = (bid / 20) * 32;
        const float* src = (n0 < NH) ? dw1 : ddp;
        int ld   = (n0 < NH) ? NH : NDD;
        int ncol = (n0 < NH) ? (n0 + tx) : (n0 - NH + tx);
        #pragma unroll
        for (int j = 0; j < 4; ++j)
            t[ty + 8 * j][tx] = src[(size_t)(k0 + ty + 8 * j) * ld + ncol];
        __syncthreads();
        #pragma unroll
        for (int j = 0; j < 4; ++j) {
            int n = n0 + ty + 8 * j, k = k0 + tx;
            g_Wh[(size_t)n * DDIM + k] = __float2half_rn(t[tx][ty + 8 * j]);
        }
    } else {
        int qb = bid - 2560;                 // 0..63
        int c  = qb >> 4;
        int j0 = ((qb >> 2) & 3) * 32;
        int k0 = (qb & 3) * 32;
        #pragma unroll
        for (int jj = 0; jj < 4; ++jj)
            t[ty + 8 * jj][tx] = qkw[((c * KDIM) + (k0 + ty + 8 * jj)) * KDIM + j0 + tx];
        __syncthreads();
        #pragma unroll
        for (int jj = 0; jj < 4; ++jj) {
            int j = j0 + ty + 8 * jj, k = k0 + tx;
            g_Qh[(c * KDIM + j) * KDIM + k] = __float2half_rn(t[tx][ty + 8 * jj]);
        }
    }
}

// ---------------------------------------------------------------------------
// gemm_all: 512 CTAs (one occ-4 wave). CTA (ntile, mbase) computes:
//   hidden cols [ntile*128, +128) x 64 rows  -> fused 2nd GEMM + RMS -> w1n/w2
//   dd cols     [ntile*32,  +32)  x 64 rows  -> tanh -> dd
// CTA 64x160-equivalent, BK=32, 128 threads (warp grid 2Mx2N for hidden;
// dd n-split by nw = wid>>1), occ 4.
// Smem (48K): mainloop A 2x4K [0,8K) + W 4x10K [8K,48K) (W tile = 160 rows);
// epilogue Ahi [0,16K), Q double-buffer [16K,32K)+[32K,48K).
// ---------------------------------------------------------------------------
#define ABUF_B  4096
#define WST_B   10240
#define W_OFF   8192
#define GEMM1_SMEM 49152

__global__ __launch_bounds__(128, 4) void gemm_all(
    const float* __restrict__ X,
    float* __restrict__ w1n_out, float* __restrict__ w2_out,
    float* __restrict__ dd_out) {
    extern __shared__ char smem[];
    uint32_t sb = smem_u32(smem);

    const int tid  = threadIdx.x;
    const int wid  = tid >> 5;
    const int lane = tid & 31;
    const int gq   = lane >> 2;
    const int tg   = lane & 3;

    const int ntile = blockIdx.x;          // 0..3
    const int mbase = blockIdx.y << 6;     // 64-row tiles
    const int m0w   = (wid & 1) * 32;
    const int n0w   = (wid >> 1) * 64;
    const int nw    = wid >> 1;            // dd n-half 0..1

    const float* Xrow = X + (size_t)mbase * DDIM;

    // A LDG geometry: 64 rows x 32 k f32 = 512 16B chunks -> 4 per thread
    int aRow[4], aCh[4];
    uint32_t aSts[4];
    #pragma unroll
    for (int q = 0; q < 4; ++q) {
        int cc = tid + q * 128;
        aRow[q] = cc >> 3; aCh[q] = cc & 7;
        aSts[q] = (uint32_t)(aRow[q] * 64
                + ((((aCh[q] >> 1) ^ ((aRow[q] >> 1) & 3)) << 4) + ((aCh[q] & 1) << 3)));
    }
    // W cp.async geometry: 160 rows x 64B = 640 chunks -> 5 per thread
    uint32_t wDst[5];
    const __half* wSrc[5];
    #pragma unroll
    for (int q = 0; q < 5; ++q) {
        int cc = tid + q * 128;
        int r = cc >> 2, ch = cc & 3;
        wDst[q] = (uint32_t)(r * 64 + ((ch ^ ((r >> 1) & 3)) << 4));
        int grow = (r < 128) ? (ntile * 128 + r) : (NH + ntile * 32 + (r - 128));
        wSrc[q] = g_Wh + (size_t)grow * DDIM + ch * 8;
    }

    auto w_refill = [&](uint32_t stg, int k0) {
        #pragma unroll
        for (int q = 0; q < 5; ++q)
            CPA16(stg + wDst[q], wSrc[q] + k0);
    };

    float4 xreg[4];
    auto a_ldg = [&](int k0) {
        #pragma unroll
        for (int q = 0; q < 4; ++q)
            xreg[q] = *reinterpret_cast<const float4*>(
                &Xrow[(size_t)aRow[q] * DDIM + k0 + aCh[q] * 4]);
    };
    auto a_sts = [&](uint32_t abuf) {
        #pragma unroll
        for (int q = 0; q < 4; ++q) {
            float4 v = xreg[q];
            uint32_t h0 = pack_h2(v.x, v.y), h1 = pack_h2(v.z, v.w);
            uint32_t a = abuf + aSts[q];
            asm volatile("st.shared.v2.u32 [%0], {%1,%2};" :: "r"(a), "r"(h0), "r"(h1) : "memory");
        }
    };

    // ldmatrix lane geometry
    const int rowAoff = ((lane >> 3) & 1) * 8 + (lane & 7);
    const int cAoff   = (lane >> 4) & 1;
    const int rowBoff = ((lane >> 4) & 1) * 8 + (lane & 7);
    const int cBoff   = (lane >> 3) & 1;

    // ---- prologue ----
    a_ldg(0);
    a_sts(sb);
    a_ldg(32);
    w_refill(sb + W_OFF, 0);              CPA_COMMIT();
    w_refill(sb + W_OFF + WST_B, 32);     CPA_COMMIT();
    w_refill(sb + W_OFF + 2 * WST_B, 64); CPA_COMMIT();

    float acc[2][8][4];
    float accD[2][2][4];
    #pragma unroll
    for (int mi = 0; mi < 2; ++mi) {
        #pragma unroll
        for (int ni = 0; ni < 8; ++ni)
            #pragma unroll
            for (int r = 0; r < 4; ++r) acc[mi][ni][r] = 0.0f;
        #pragma unroll
        for (int ni = 0; ni < 2; ++ni)
            #pragma unroll
            for (int r = 0; r < 4; ++r) accD[mi][ni][r] = 0.0f;
    }

    const int NKT = DDIM / 32;  // 128

    for (int it = 0; it < NKT; ++it) {
        uint32_t abuf = sb + (uint32_t)(it & 1) * ABUF_B;
        uint32_t wstg = sb + W_OFF + (uint32_t)(it & 3) * WST_B;

        CPA_WAIT2();
        __syncthreads();

        if (it + 1 < NKT) a_sts(sb + (uint32_t)((it + 1) & 1) * ABUF_B);
        if (it + 2 < NKT) a_ldg((it + 2) * 32);

        #pragma unroll
        for (int ks = 0; ks < 2; ++ks) {
            int c0 = ks * 2;
            uint32_t bh[8][2], bd[2][2];
            #pragma unroll
            for (int p = 0; p < 4; ++p) {
                int rowB = n0w + p * 16 + rowBoff;
                int cB   = c0 + cBoff;
                uint32_t aW = wstg + rowB * 64
                            + (uint32_t)((cB ^ ((rowB >> 1) & 3)) << 4);
                uint32_t t[4];
                ldsm_x4(aW, t);
                bh[2*p][0] = t[0]; bh[2*p][1] = t[1];
                bh[2*p+1][0] = t[2]; bh[2*p+1][1] = t[3];
            }
            {   // dd W frags: rows 128 + nw*16 .. +16
                int rowD = 128 + nw * 16 + rowBoff;
                int cB   = c0 + cBoff;
                uint32_t aD = wstg + rowD * 64
                            + (uint32_t)((cB ^ ((rowD >> 1) & 3)) << 4);
                uint32_t t[4];
                ldsm_x4(aD, t);
                bd[0][0] = t[0]; bd[0][1] = t[1];
                bd[1][0] = t[2]; bd[1][1] = t[3];
            }
            #pragma unroll
            for (int mi = 0; mi < 2; ++mi) {
                int rowA = m0w + mi * 16 + rowAoff;
                int cA   = c0 + cAoff;
                uint32_t aA = abuf + rowA * 64
                            + (uint32_t)((cA ^ ((rowA >> 1) & 3)) << 4);
                uint32_t ah[4];
                ldsm_x4(aA, ah);
                #pragma unroll
                for (int ni = 0; ni < 8; ++ni)
                    mma16816(acc[mi][ni], ah, bh[ni]);
                mma16816(accD[mi][0], ah, bd[0]);
                mma16816(accD[mi][1], ah, bd[1]);
            }
        }

        if (it + 3 < NKT)
            w_refill(sb + W_OFF + (uint32_t)((it + 3) & 3) * WST_B, (it + 3) * 32);
        CPA_COMMIT();
    }

    CPA_WAIT0();
    __syncthreads();

    // ---- dd epilogue first (frees accD registers) ----
    #pragma unroll
    for (int mi = 0; mi < 2; ++mi) {
        #pragma unroll
        for (int fi = 0; fi < 2; ++fi) {
            int row = mbase + m0w + mi * 16 + gq;
            int col = ntile * 32 + nw * 16 + fi * 8 + tg * 2;
            float2 o0 = make_float2(tanhf(accD[mi][fi][0]), tanhf(accD[mi][fi][1]));
            float2 o1 = make_float2(tanhf(accD[mi][fi][2]), tanhf(accD[mi][fi][3]));
            *reinterpret_cast<float2*>(&dd_out[(size_t)row * NDD + col])       = o0;
            *reinterpret_cast<float2*>(&dd_out[(size_t)(row + 8) * NDD + col]) = o1;
        }
    }

    // ================= fused hidden epilogue =================
    const int c = ntile;
    const uint32_t qb0 = sb + 16384;   // Q kb=0 [16K,32K)
    const uint32_t qb1 = sb + 32768;   // Q kb=1 [32K,48K)

    // Issue BOTH Q halves now; they land under the gelu/STS phase below.
    #pragma unroll
    for (int q = 0; q < 8; ++q) {
        int cc = tid + q * 128;
        int j  = cc >> 3, ch = cc & 7;
        uint32_t off = (uint32_t)(j * 128 + ((ch ^ (j & 7)) << 4));
        CPA16(qb0 + off, g_Qh + ((size_t)(c * KDIM + j)) * KDIM + ch * 8);
    }
    CPA_COMMIT();
    #pragma unroll
    for (int q = 0; q < 8; ++q) {
        int cc = tid + q * 128;
        int j  = cc >> 3, ch = cc & 7;
        uint32_t off = (uint32_t)(j * 128 + ((ch ^ (j & 7)) << 4));
        CPA16(qb1 + off, g_Qh + ((size_t)(c * KDIM + j)) * KDIM + 64 + ch * 8);
    }
    CPA_COMMIT();

    // Phase 1: gelu -> fp16 single-term into Ahi [0,16K)
    #pragma unroll
    for (int mi = 0; mi < 2; ++mi) {
        #pragma unroll
        for (int ni = 0; ni < 8; ++ni) {
            int row0 = m0w + mi * 16 + gq;
            int col  = n0w + ni * 8 + tg * 2;
            uint32_t ch = (uint32_t)(col >> 3);
            uint32_t wi = (uint32_t)((col & 7) * 2);
            #pragma unroll
            for (int r2 = 0; r2 < 2; ++r2) {
                int row = row0 + r2 * 8;
                float v0 = gelu_exact(acc[mi][ni][2 * r2 + 0]);
                float v1 = gelu_exact(acc[mi][ni][2 * r2 + 1]);
                uint32_t h = pack_h2(v0, v1);
                uint32_t a = sb + row * 256 + ((ch ^ (uint32_t)(row & 7)) << 4) + wi;
                asm volatile("st.shared.u32 [%0], %1;" :: "r"(a), "r"(h) : "memory");
            }
        }
    }

    // Phase 2: 64x128x128 single-term MMA (hh*qh), f32 acc, Q double-buffered
    float acc2[2][8][4];
    #pragma unroll
    for (int mi = 0; mi < 2; ++mi)
        #pragma unroll
        for (int ni = 0; ni < 8; ++ni)
            #pragma unroll
            for (int r = 0; r < 4; ++r) acc2[mi][ni][r] = 0.0f;

    for (int kb = 0; kb < 2; ++kb) {
        uint32_t qb = kb ? qb1 : qb0;
        if (kb == 0) { CPA_WAIT1(); } else { CPA_WAIT0(); }
        __syncthreads();

        #pragma unroll
        for (int ksl = 0; ksl < 4; ++ksl) {
            uint32_t qh[8][2];
            #pragma unroll
            for (int p = 0; p < 4; ++p) {
                int rowB = n0w + p * 16 + rowBoff;
                int cB   = ksl * 2 + cBoff;
                uint32_t aW = qb + rowB * 128
                            + (uint32_t)((cB ^ (rowB & 7)) << 4);
                uint32_t t[4];
                ldsm_x4(aW, t);
                qh[2*p][0] = t[0]; qh[2*p][1] = t[1];
                qh[2*p+1][0] = t[2]; qh[2*p+1][1] = t[3];
            }
            #pragma unroll
            for (int mi = 0; mi < 2; ++mi) {
                int rowA = m0w + mi * 16 + rowAoff;
                int cA   = kb * 8 + ksl * 2 + cAoff;
                uint32_t aA = sb + rowA * 256
                            + (uint32_t)((cA ^ (rowA & 7)) << 4);
                uint32_t ah[4];
                ldsm_x4(aA, ah);
                #pragma unroll
                for (int ni = 0; ni < 8; ++ni)
                    mma16816(acc2[mi][ni], ah, qh[ni]);
            }
        }
    }

    // Phase 3: RMS over 32-col groups + stores
    const int iiA = n0w >> 5;     // 0 (w1n pair) or 2 (w2 pair)
    #pragma unroll
    for (int mi = 0; mi < 2; ++mi) {
        #pragma unroll
        for (int r2 = 0; r2 < 2; ++r2) {
            int r = mbase + m0w + mi * 16 + gq + r2 * 8;
            float ssA = 0.0f, ssB = 0.0f;
            #pragma unroll
            for (int ni = 0; ni < 4; ++ni) {
                ssA = fmaf(acc2[mi][ni][2*r2+0], acc2[mi][ni][2*r2+0], ssA);
                ssA = fmaf(acc2[mi][ni][2*r2+1], acc2[mi][ni][2*r2+1], ssA);
                ssB = fmaf(acc2[mi][ni+4][2*r2+0], acc2[mi][ni+4][2*r2+0], ssB);
                ssB = fmaf(acc2[mi][ni+4][2*r2+1], acc2[mi][ni+4][2*r2+1], ssB);
            }
            ssA += __shfl_xor_sync(0xffffffffu, ssA, 1);
            ssA += __shfl_xor_sync(0xffffffffu, ssA, 2);
            ssB += __shfl_xor_sync(0xffffffffu, ssB, 1);
            ssB += __shfl_xor_sync(0xffffffffu, ssB, 2);

            if (iiA == 0) {
                float scA = rsqrtf(ssA * (1.0f / 32.0f) + 1e-6f);
                float scB = rsqrtf(ssB * (1.0f / 32.0f) + 1e-6f);
                #pragma unroll
                for (int ni = 0; ni < 4; ++ni) {
                    int m = ni * 8 + tg * 2;
                    float2 oA = make_float2(acc2[mi][ni][2*r2+0] * scA,
                                            acc2[mi][ni][2*r2+1] * scA);
                    float2 oB = make_float2(acc2[mi][ni+4][2*r2+0] * scB,
                                            acc2[mi][ni+4][2*r2+1] * scB);
                    *reinterpret_cast<float2*>(
                        &w1n_out[(size_t)r * 256 + c * 64 + m]) = oA;
                    *reinterpret_cast<float2*>(
                        &w1n_out[(size_t)r * 256 + c * 64 + 32 + m]) = oB;
                }
            } else {
                #pragma unroll
                for (int ni = 0; ni < 4; ++ni) {
                    int m = ni * 8 + tg * 2;
                    float2 oA = make_float2(acc2[mi][ni][2*r2+0],
                                            acc2[mi][ni][2*r2+1]);
                    float2 oB = make_float2(acc2[mi][ni+4][2*r2+0],
                                            acc2[mi][ni+4][2*r2+1]);
                    *reinterpret_cast<float2*>(
                        &w2_out[(size_t)r * 256 + c * 64 + m]) = oA;
                    *reinterpret_cast<float2*>(
                        &w2_out[(size_t)r * 256 + c * 64 + 32 + m]) = oB;
                }
            }
        }
    }
}

// ---------------------------------------------------------------------------
extern "C" void kernel_launch(void* const* d_in, const int* in_sizes, int n_in,
                              void* d_out, int out_size) {
    const float* query = (const float*)d_in[0];
    // d_in[1] = key_vec (unused by reference)
    const float* dw1   = (const float*)d_in[2];
    const float* qkw   = (const float*)d_in[3];
    const float* dd_p  = (const float*)d_in[4];

    float* out = (float*)d_out;
    float* w1n = out;
    float* w2  = out + W2_BASE;
    float* dd  = out + DD_BASE;

    cudaFuncSetAttribute(gemm_all, cudaFuncAttributeMaxDynamicSharedMemorySize, GEMM1_SMEM);

    conv_wq<<<2624, dim3(32, 8)>>>(dw1, dd_p, qkw);
    gemm_all<<<dim3(4, 128), 128, GEMM1_SMEM>>>(query, w1n, w2, dd);
}